// round 15
// baseline (speedup 1.0000x reference)
#include <cuda_runtime.h>
#include <cuda_bf16.h>
#include <cstdint>

// KinematicWaveRouting via the scalar transfer function of the 20-segment chain.
//   y_t = y_{t-1} + u_t - sum_{j=0..7} c_j u_{t-20-j},   u = runoff * basin * 50
//   8-tap NegBinomial kernel, two-moment matched (rel err ~1.8e-4, thresh 1e-3).
// One warp per row, lane = 128-step chunk, warm-started 32 steps early.
// R15: TRIPLE-buffered input/output tiles (A/B/C), prefetch distance 2:
//   phase g issues group g+2's cp.async batch into the buffer drained at g-1,
//   and cpwait's a batch issued TWO phases (~6K cyc) ago -> waits never block.
// 55.3KB smem/block (dynamic, attribute raised), 4 blocks/SM = 16 warps that
// should be stall-free; DRAM throughput becomes the pacing constraint.
// Tile rows 144B chunk-major; 16B cp.async, LDS.128, STS.128 in-place,
// LDS.128 + STG.128.cs drain. All smem phases conflict-free.

#define T_LEN    4096
#define CHUNK    128
#define NCHUNK   32
#define RPB      4
#define NTAPS    8
#define TSTRIDE  36                      // floats per tile row (144 bytes)
#define SERIES   (NCHUNK * TSTRIDE)      // 1152 floats per warp-buffer
#define SMEM_BYTES (3 * RPB * SERIES * 4)   // 55296

// -c'_m, m = 20..27 (two-moment matched)
static __device__ constexpr float CNEG[NTAPS] = {
    -0.12252114f, -0.24315331f, -0.25531098f, -0.18722805f,
    -0.10362058f, -0.05167495f, -0.02153122f, -0.01495978f
};
// warm-start weights g'_m = 1 - cumsum(c'), lags 20..26 (g'_27 = 0)
static __device__ constexpr float GW[7] = {
    0.87747886f, 0.63432555f, 0.37901458f, 0.19178653f,
    0.08816595f, 0.03649100f, 0.01495978f
};

__device__ __forceinline__ void cpasync16(uint32_t s, const float* g) {
    asm volatile("cp.async.cg.shared.global [%0], [%1], 16;" :: "r"(s), "l"(g) : "memory");
}
__device__ __forceinline__ void cpcommit() {
    asm volatile("cp.async.commit_group;" ::: "memory");
}
template <int N>
__device__ __forceinline__ void cpwait() {
    asm volatile("cp.async.wait_group %0;" :: "n"(N) : "memory");
}
__device__ __forceinline__ void sts128(uint32_t a, float v0, float v1, float v2, float v3) {
    asm volatile("st.shared.v4.f32 [%0], {%1, %2, %3, %4};"
                 :: "r"(a), "f"(v0), "f"(v1), "f"(v2), "f"(v3) : "memory");
}
__device__ __forceinline__ void stg128cs(float* p, float4 v) {
    asm volatile("st.global.cs.v4.f32 [%0], {%1, %2, %3, %4};"
                 :: "l"(p), "f"(v.x), "f"(v.y), "f"(v.z), "f"(v.w) : "memory");
}

// Prefetch group GIDX: 8 x 16B cp.async per lane; instruction i covers chunks
// 4i..4i+3. rq = rrow + (lane>>3)*CHUNK + (lane&7)*4 - 32.
#define PREFETCH(TU, GIDX)                                                  \
    do {                                                                    \
        _Pragma("unroll")                                                   \
        for (int i = 0; i < 8; i++)                                         \
            cpasync16((TU) + i * 576, rq + i * 512 + (GIDX) * 32);          \
        cpcommit();                                                         \
    } while (0)

// Load the lane's 32 inputs (own chunk row): 8 x LDS.128, conflict-free.
#define LOAD_W(W, TB)                                                       \
    do {                                                                    \
        const float4* r4 = (const float4*)((TB) + lane * TSTRIDE);          \
        _Pragma("unroll")                                                   \
        for (int k = 0; k < 8; k++) {                                       \
            float4 t = r4[k];                                               \
            W[4 * k] = t.x; W[4 * k + 1] = t.y;                             \
            W[4 * k + 2] = t.z; W[4 * k + 3] = t.w;                         \
        }                                                                   \
    } while (0)

// 32 steps as 8 quads; scaled outputs overwrite the lane's own row in place.
#define GROUP_BODY(PREV, CUR, TROWU)                                        \
    do {                                                                    \
        _Pragma("unroll")                                                   \
        for (int qq = 0; qq < 8; qq++) {                                    \
            float vv[4];                                                    \
            _Pragma("unroll")                                               \
            for (int s = 0; s < 4; s++) {                                   \
                const int m = 4 * qq + s;                                   \
                float acc = CUR[m];                                         \
                _Pragma("unroll")                                           \
                for (int j = 0; j < NTAPS; j++) {                           \
                    const int k = m - (20 + j);                             \
                    float w = (k >= 0) ? CUR[k] : PREV[32 + k];             \
                    acc = fmaf(CNEG[j], w, acc);                            \
                }                                                           \
                y += acc;                                                   \
                vv[s] = y * scale;                                          \
            }                                                               \
            sts128((TROWU) + qq * 16, vv[0], vv[1], vv[2], vv[3]);          \
        }                                                                   \
    } while (0)

// Drain group GIDX: lane handles (chunk = 4k + (lane>>3), quad = lane&7):
// LDS.128 from the chunk-major tile, STG.128.cs covering full 128B lines.
#define DRAIN(TB, GIDX)                                                     \
    do {                                                                    \
        const float* sp = (TB) + (lane >> 3) * TSTRIDE + (lane & 7) * 4;    \
        float* gp = odrain + ((GIDX) - 1) * 32;                             \
        _Pragma("unroll")                                                   \
        for (int k = 0; k < 8; k++) {                                       \
            float4 v = *(const float4*)(sp + k * 4 * TSTRIDE);              \
            stg128cs(gp + k * 512, v);                                      \
        }                                                                   \
    } while (0)

__global__ __launch_bounds__(128, 4)
void kinematic_wave_kernel(const float* __restrict__ runoff,
                           const float* __restrict__ basin,
                           float* __restrict__ out,
                           int B)
{
    extern __shared__ __align__(16) float smem[];

    const int warp = threadIdx.x >> 5;
    const int lane = threadIdx.x & 31;
    const int row  = blockIdx.x * RPB + warp;
    if (row >= B) return;

    float* A  = smem + warp * SERIES;                 // buffer 0
    float* Bb = A + RPB * SERIES;                     // buffer 1
    float* C  = Bb + RPB * SERIES;                    // buffer 2

    const uint32_t lslot = (uint32_t)((lane >> 3) * 144 + (lane & 7) * 16);
    const uint32_t rslot = (uint32_t)(lane * 144);
    const uint32_t Au = (uint32_t)__cvta_generic_to_shared(A);
    const uint32_t Bu = Au + RPB * SERIES * 4;
    const uint32_t Cu = Bu + RPB * SERIES * 4;

    const float scale = basin[row] * 50.0f;
    const float* __restrict__ rq =
        runoff + (size_t)row * T_LEN + (lane >> 3) * CHUNK + (lane & 7) * 4 - 32;
    float* __restrict__ odrain =
        out + (size_t)row * T_LEN + (lane >> 3) * CHUNK + (lane & 7) * 4;

    float W0[32], W1[32], y;

    // ---- warm fill -> A (chunk 0 is all t<0 -> zeros); prefetch G1->B, G2->C
    A[lane] = 0.0f;                                   // chunk-0 row, float = lane
#pragma unroll
    for (int i = 0; i < 8; i++) {
        if (i == 0) { if ((lane >> 3) != 0) cpasync16(Au + lslot, rq); }
        else cpasync16(Au + lslot + i * 576, rq + i * 512);
    }
    cpcommit();
    PREFETCH(Bu + lslot, 1);
    PREFETCH(Cu + lslot, 2);
    cpwait<2>(); __syncwarp();                        // warm batch landed
    LOAD_W(W0, A);
    // warm FIR: W0[j] = u(t0-32+j), lag = 31-j; y = outlet at t0-1 (unscaled)
    {
        float s = 0.0f;
#pragma unroll
        for (int j = 12; j < 32; j++) s += W0[j];                 // lags 0..19
        float s2 = 0.0f;
#pragma unroll
        for (int j = 5; j < 12; j++) s2 = fmaf(GW[11 - j], W0[j], s2); // 20..26
        y = s + s2;
    }
    __syncwarp();                                     // A fully consumed

    // ---- group 1: inputs in B; prefetch G3 -> A (distance 2) ----
    PREFETCH(Au + lslot, 3);
    cpwait<2>(); __syncwarp();                        // G1 batch: issued 2 phases ago
    LOAD_W(W1, Bb);
    GROUP_BODY(W0, W1, Bu + rslot);
    __syncwarp();
    DRAIN(Bb, 1);
    __syncwarp();

    // ---- group 2: inputs in C; prefetch G4 -> B ----
    PREFETCH(Bu + lslot, 4);
    cpwait<2>(); __syncwarp();
    LOAD_W(W0, C);
    GROUP_BODY(W1, W0, Cu + rslot);
    __syncwarp();
    DRAIN(C, 2);
    __syncwarp();

    // ---- group 3: inputs in A ----
    cpwait<1>(); __syncwarp();
    LOAD_W(W1, A);
    GROUP_BODY(W0, W1, Au + rslot);
    __syncwarp();
    DRAIN(A, 3);
    __syncwarp();

    // ---- group 4: inputs in B ----
    cpwait<0>(); __syncwarp();
    LOAD_W(W0, Bb);
    GROUP_BODY(W1, W0, Bu + rslot);
    __syncwarp();
    DRAIN(Bb, 4);
}

extern "C" void kernel_launch(void* const* d_in, const int* in_sizes, int n_in,
                              void* d_out, int out_size)
{
    const float* runoff = (const float*)d_in[0];   // (B, T) float32
    const float* basin  = (const float*)d_in[1];   // (B, 1) float32
    float* out = (float*)d_out;                    // (B, T) float32

    int B = in_sizes[1];                           // 8192
    int blocks = (B + RPB - 1) / RPB;              // 2048

    // 55.3KB dynamic smem (> 48KB static limit). Unconditional + deterministic;
    // attribute set executes immediately (not a stream op), capture-safe.
    cudaFuncSetAttribute(kinematic_wave_kernel,
                         cudaFuncAttributeMaxDynamicSharedMemorySize, SMEM_BYTES);
    kinematic_wave_kernel<<<blocks, 128, SMEM_BYTES>>>(runoff, basin, out, B);
}

// round 16
// speedup vs baseline: 1.0358x; 1.0358x over previous
#include <cuda_runtime.h>
#include <cuda_bf16.h>
#include <cstdint>

// KinematicWaveRouting via the scalar transfer function of the 20-segment chain.
//   y_t = y_{t-1} + u_t - sum_{j=0..7} c_j u_{t-20-j},   u = runoff * basin * 50
//   8-tap NegBinomial kernel, two-moment matched (rel err ~1.8e-4, thresh 1e-3).
// One warp per row, lane = 128-step chunk, warm-started 32 steps early.
// R16: ZERO-HALO. The warm window of lane l = last 32 steps of chunk l-1 =
// group-4 inputs of lane l-1. A third persistent buffer Z holds the group-4
// slice of every chunk, fetched ONCE up front: warm FIR reads Z row (lane-1)
// (lane 0 -> zeros), group 4 consumes Z directly with no fetch. Every input
// float is read from DRAM exactly once (reads -20% vs R14).
// 55.3KB smem/block (dynamic), 4 blocks/SM. Tile rows 144B chunk-major;
// 16B cp.async, LDS.128 loads, STS.128 in-place outputs, LDS.128+STG.128.cs
// drain. All smem phases conflict-free.

#define T_LEN    4096
#define CHUNK    128
#define NCHUNK   32
#define RPB      4
#define NTAPS    8
#define TSTRIDE  36                      // floats per tile row (144 bytes)
#define SERIES   (NCHUNK * TSTRIDE)      // 1152 floats per warp-buffer
#define SMEM_BYTES (3 * RPB * SERIES * 4)   // 55296

// -c'_m, m = 20..27 (two-moment matched)
static __device__ constexpr float CNEG[NTAPS] = {
    -0.12252114f, -0.24315331f, -0.25531098f, -0.18722805f,
    -0.10362058f, -0.05167495f, -0.02153122f, -0.01495978f
};
// warm-start weights g'_m = 1 - cumsum(c'), lags 20..26 (g'_27 = 0)
static __device__ constexpr float GW[7] = {
    0.87747886f, 0.63432555f, 0.37901458f, 0.19178653f,
    0.08816595f, 0.03649100f, 0.01495978f
};

__device__ __forceinline__ void cpasync16(uint32_t s, const float* g) {
    asm volatile("cp.async.cg.shared.global [%0], [%1], 16;" :: "r"(s), "l"(g) : "memory");
}
__device__ __forceinline__ void cpcommit() {
    asm volatile("cp.async.commit_group;" ::: "memory");
}
template <int N>
__device__ __forceinline__ void cpwait() {
    asm volatile("cp.async.wait_group %0;" :: "n"(N) : "memory");
}
__device__ __forceinline__ void sts128(uint32_t a, float v0, float v1, float v2, float v3) {
    asm volatile("st.shared.v4.f32 [%0], {%1, %2, %3, %4};"
                 :: "r"(a), "f"(v0), "f"(v1), "f"(v2), "f"(v3) : "memory");
}
__device__ __forceinline__ void stg128cs(float* p, float4 v) {
    asm volatile("st.global.cs.v4.f32 [%0], {%1, %2, %3, %4};"
                 :: "l"(p), "f"(v.x), "f"(v.y), "f"(v.z), "f"(v.w) : "memory");
}

// Prefetch group GIDX (1..4): 8 x 16B cp.async per lane; instruction i covers
// chunks 4i..4i+3. rq = rrow + (lane>>3)*CHUNK + (lane&7)*4 - 32.
// GIDX=4 fetches each chunk's tail slice [96,128) = the Z / halo tile.
#define PREFETCH(TU, GIDX)                                                  \
    do {                                                                    \
        _Pragma("unroll")                                                   \
        for (int i = 0; i < 8; i++)                                         \
            cpasync16((TU) + i * 576, rq + i * 512 + (GIDX) * 32);          \
        cpcommit();                                                         \
    } while (0)

// Load 32 inputs from row `lane` of TB: 8 x LDS.128, conflict-free.
// (Pass TB - TSTRIDE to read row lane-1.)
#define LOAD_W(W, TB)                                                       \
    do {                                                                    \
        const float4* r4 = (const float4*)((TB) + lane * TSTRIDE);          \
        _Pragma("unroll")                                                   \
        for (int k = 0; k < 8; k++) {                                       \
            float4 t = r4[k];                                               \
            W[4 * k] = t.x; W[4 * k + 1] = t.y;                             \
            W[4 * k + 2] = t.z; W[4 * k + 3] = t.w;                         \
        }                                                                   \
    } while (0)

// 32 steps as 8 quads; scaled outputs overwrite the lane's own row in place.
#define GROUP_BODY(PREV, CUR, TROWU)                                        \
    do {                                                                    \
        _Pragma("unroll")                                                   \
        for (int qq = 0; qq < 8; qq++) {                                    \
            float vv[4];                                                    \
            _Pragma("unroll")                                               \
            for (int s = 0; s < 4; s++) {                                   \
                const int m = 4 * qq + s;                                   \
                float acc = CUR[m];                                         \
                _Pragma("unroll")                                           \
                for (int j = 0; j < NTAPS; j++) {                           \
                    const int k = m - (20 + j);                             \
                    float w = (k >= 0) ? CUR[k] : PREV[32 + k];             \
                    acc = fmaf(CNEG[j], w, acc);                            \
                }                                                           \
                y += acc;                                                   \
                vv[s] = y * scale;                                          \
            }                                                               \
            sts128((TROWU) + qq * 16, vv[0], vv[1], vv[2], vv[3]);          \
        }                                                                   \
    } while (0)

// Drain group GIDX: lane handles (chunk = 4k + (lane>>3), quad = lane&7):
// LDS.128 from the chunk-major tile, STG.128.cs covering full 128B lines.
#define DRAIN(TB, GIDX)                                                     \
    do {                                                                    \
        const float* sp = (TB) + (lane >> 3) * TSTRIDE + (lane & 7) * 4;    \
        float* gp = odrain + ((GIDX) - 1) * 32;                             \
        _Pragma("unroll")                                                   \
        for (int k = 0; k < 8; k++) {                                       \
            float4 v = *(const float4*)(sp + k * 4 * TSTRIDE);              \
            stg128cs(gp + k * 512, v);                                      \
        }                                                                   \
    } while (0)

__global__ __launch_bounds__(128, 4)
void kinematic_wave_kernel(const float* __restrict__ runoff,
                           const float* __restrict__ basin,
                           float* __restrict__ out,
                           int B)
{
    extern __shared__ __align__(16) float smem[];

    const int warp = threadIdx.x >> 5;
    const int lane = threadIdx.x & 31;
    const int row  = blockIdx.x * RPB + warp;
    if (row >= B) return;

    float* X = smem + warp * SERIES;
    float* Y = X + RPB * SERIES;
    float* Z = Y + RPB * SERIES;                     // persistent tail/halo tile

    const uint32_t lslot = (uint32_t)((lane >> 3) * 144 + (lane & 7) * 16);
    const uint32_t rslot = (uint32_t)(lane * 144);
    const uint32_t Xu = (uint32_t)__cvta_generic_to_shared(X);
    const uint32_t Yu = Xu + RPB * SERIES * 4;
    const uint32_t Zu = Yu + RPB * SERIES * 4;

    const float scale = basin[row] * 50.0f;
    const float* __restrict__ rq =
        runoff + (size_t)row * T_LEN + (lane >> 3) * CHUNK + (lane & 7) * 4 - 32;
    float* __restrict__ odrain =
        out + (size_t)row * T_LEN + (lane >> 3) * CHUNK + (lane & 7) * 4;

    float W0[32], W1[32], y;

    // ---- fetch Z (all chunk tails), G1 -> X, G2 -> Y ----
    PREFETCH(Zu + lslot, 4);     // commit 1: Z (tail slices, = halos)
    PREFETCH(Xu + lslot, 1);     // commit 2: group-1 inputs
    PREFETCH(Yu + lslot, 2);     // commit 3: group-2 inputs
    cpwait<2>(); __syncwarp();   // Z landed

    // warm window: Z row (lane-1) = chunk (lane-1) steps [96,128) = [t0-32, t0)
    if (lane > 0) {
        LOAD_W(W0, Z - TSTRIDE);
    } else {
#pragma unroll
        for (int j = 0; j < 32; j++) W0[j] = 0.0f;   // chunk 0: t < 0
    }
    // warm FIR: W0[j] = u(t0-32+j), lag = 31-j; y = outlet at t0-1 (unscaled)
    {
        float s = 0.0f;
#pragma unroll
        for (int j = 12; j < 32; j++) s += W0[j];                 // lags 0..19
        float s2 = 0.0f;
#pragma unroll
        for (int j = 5; j < 12; j++) s2 = fmaf(GW[11 - j], W0[j], s2); // 20..26
        y = s + s2;
    }

    // ---- group 1: inputs in X ----
    cpwait<1>(); __syncwarp();                       // X landed (Z,X done)
    LOAD_W(W1, X);
    GROUP_BODY(W0, W1, Xu + rslot);
    __syncwarp();
    DRAIN(X, 1);
    __syncwarp();
    PREFETCH(Xu + lslot, 3);     // commit 4: group-3 inputs -> X (post-drain)

    // ---- group 2: inputs in Y ----
    cpwait<1>(); __syncwarp();                       // Y landed (G3 may pend)
    LOAD_W(W0, Y);
    GROUP_BODY(W1, W0, Yu + rslot);
    __syncwarp();
    DRAIN(Y, 2);

    // ---- group 3: inputs in X ----
    cpwait<0>(); __syncwarp();                       // G3 landed
    LOAD_W(W1, X);
    GROUP_BODY(W0, W1, Xu + rslot);
    __syncwarp();
    DRAIN(X, 3);
    __syncwarp();

    // ---- group 4: inputs already resident in Z (no fetch) ----
    LOAD_W(W0, Z);
    GROUP_BODY(W1, W0, Zu + rslot);
    __syncwarp();
    DRAIN(Z, 4);
}

extern "C" void kernel_launch(void* const* d_in, const int* in_sizes, int n_in,
                              void* d_out, int out_size)
{
    const float* runoff = (const float*)d_in[0];   // (B, T) float32
    const float* basin  = (const float*)d_in[1];   // (B, 1) float32
    float* out = (float*)d_out;                    // (B, T) float32

    int B = in_sizes[1];                           // 8192
    int blocks = (B + RPB - 1) / RPB;              // 2048

    // 55.3KB dynamic smem (> 48KB static limit); attribute set is immediate
    // (not a stream op) and deterministic -> graph-capture safe.
    cudaFuncSetAttribute(kinematic_wave_kernel,
                         cudaFuncAttributeMaxDynamicSharedMemorySize, SMEM_BYTES);
    kinematic_wave_kernel<<<blocks, 128, SMEM_BYTES>>>(runoff, basin, out, B);
}